// round 10
// baseline (speedup 1.0000x reference)
#include <cuda_runtime.h>
#include <cuda_bf16.h>
#include <cstdint>

// PointConv2d fused (round 5): mma.sync bf16 3-term GEMM, cp.async pipelined,
// 4x2 warp tiling. B=8, N=16384, K=9, C=64 -> CIN=66, O=9, CO=64, FAN=594.

namespace {
constexpr int B_   = 8;
constexpr int N_   = 16384;
constexpr int K_   = 9;
constexpr int CF_  = 64;
constexpr int CIN_ = 66;
constexpr int O_   = 9;
constexpr int CO_  = 64;
constexpr int FAN_ = 594;

constexpr int TM      = 128;
constexpr int THREADS = 256;
constexpr int CPC     = 8;    // channels per chunk
constexpr int NCH     = 9;    // chunks
constexpr int SLOTS   = 80;   // padded k' slots per chunk
constexpr int KSTEPS  = 5;

constexpr int BSTRIDE = 176;  // B smem row stride bytes
constexpr int ASTRIDE = 256;  // A smem row stride bytes ([slot][p] bf16)

// shared memory byte offsets
constexpr int SM_PRM  = 0;                          // 181 floats -> 768
constexpr int SM_AHI  = 768;                        // 80*256 = 20480
constexpr int SM_ALO  = SM_AHI + SLOTS * ASTRIDE;   // 21248
constexpr int SM_BHI  = 42240;                      // A end 41728 + 512 pad (ws alias needs 41472)
constexpr int SM_BLO  = SM_BHI + CO_ * BSTRIDE;     // 53504
constexpr int SM_FEAT = SM_BLO + CO_ * BSTRIDE;     // 64768
constexpr int SM_TOT  = SM_FEAT + CPC * TM * K_ * 4;  // 101632
// ws alias: [SM_AHI, SM_AHI+41472) = [768, 42240)  (dead before A written)
// epilogue transpose buffer alias: SM_AHI (64*132*4 = 33792)
}

// prepacked reordered hi/lo-split linear weights: [chunk][co][88]
__device__ __nv_bfloat16 g_Bhi[NCH * CO_ * 88];
__device__ __nv_bfloat16 g_Blo[NCH * CO_ * 88];

// ---------------- helpers ----------------
__device__ __forceinline__ uint32_t smem_u32(const void* p) {
    uint32_t a;
    asm("{ .reg .u64 t; cvta.to.shared.u64 t, %1; cvt.u32.u64 %0, t; }"
        : "=r"(a) : "l"(p));
    return a;
}
__device__ __forceinline__ uint64_t pack2(float lo, float hi) {
    uint64_t r;
    asm("mov.b64 %0, {%1, %2};" : "=l"(r) : "f"(lo), "f"(hi));
    return r;
}
__device__ __forceinline__ void unpack2(uint64_t v, float& a, float& b) {
    asm("mov.b64 {%0, %1}, %2;" : "=f"(a), "=f"(b) : "l"(v));
}
__device__ __forceinline__ uint64_t fma2(uint64_t a, uint64_t b, uint64_t c) {
    uint64_t r;
    asm("fma.rn.f32x2 %0, %1, %2, %3;" : "=l"(r) : "l"(a), "l"(b), "l"(c));
    return r;
}
__device__ __forceinline__ void ldsm_x4(uint32_t* r, uint32_t a) {
    asm volatile("ldmatrix.sync.aligned.m8n8.x4.shared.b16 {%0,%1,%2,%3}, [%4];"
        : "=r"(r[0]), "=r"(r[1]), "=r"(r[2]), "=r"(r[3]) : "r"(a));
}
__device__ __forceinline__ void ldsm_x4_t(uint32_t* r, uint32_t a) {
    asm volatile("ldmatrix.sync.aligned.m8n8.x4.trans.shared.b16 {%0,%1,%2,%3}, [%4];"
        : "=r"(r[0]), "=r"(r[1]), "=r"(r[2]), "=r"(r[3]) : "r"(a));
}
__device__ __forceinline__ void mma16816(float* d, const uint32_t* a,
                                         uint32_t b0, uint32_t b1) {
    asm volatile("mma.sync.aligned.m16n8k16.row.col.f32.bf16.bf16.f32 "
        "{%0,%1,%2,%3}, {%4,%5,%6,%7}, {%8,%9}, {%0,%1,%2,%3};"
        : "+f"(d[0]), "+f"(d[1]), "+f"(d[2]), "+f"(d[3])
        : "r"(a[0]), "r"(a[1]), "r"(a[2]), "r"(a[3]), "r"(b0), "r"(b1));
}
__device__ __forceinline__ void cp16(uint32_t dst, const void* src, uint32_t bytes) {
    asm volatile("cp.async.cg.shared.global [%0], [%1], 16, %2;"
        :: "r"(dst), "l"(src), "r"(bytes) : "memory");
}
#define CP_COMMIT() asm volatile("cp.async.commit_group;" ::: "memory")
#define CP_WAIT(n)  asm volatile("cp.async.wait_group %0;" :: "n"(n) : "memory")
__device__ __forceinline__ float leaky(float x) { return fmaxf(x, 0.1f * x); }

// ---------------- prep: reorder + hi/lo split of lin_w ----------------
__global__ void pc_prep(const float* __restrict__ lw) {
    int idx = blockIdx.x * blockDim.x + threadIdx.x;
    if (idx >= NCH * CO_ * 88) return;
    const int kk = idx % 88;
    const int co = (idx / 88) % CO_;
    const int ck = idx / (88 * CO_);
    float v = 0.0f;
    if (kk < 72) {
        const int c = ck * CPC + kk / 9;
        const int o = kk % 9;
        if (c < CIN_) v = lw[co * FAN_ + o * CIN_ + c];
    }
    __nv_bfloat16 hi = __float2bfloat16(v);
    __nv_bfloat16 lo = __float2bfloat16(v - __bfloat162float(hi));
    g_Bhi[idx] = hi;
    g_Blo[idx] = lo;
}

// ---------------- main kernel ----------------
__global__ __launch_bounds__(THREADS, 2)
void pc_main(const float* __restrict__ xy,    // [B,2,N,K]
             const float* __restrict__ knnf,  // [B,64,N,K]
             const float* __restrict__ w1, const float* __restrict__ b1,
             const float* __restrict__ w2, const float* __restrict__ b2,
             const float* __restrict__ lb,    // [64]
             float* __restrict__ out)         // [B,64,N]
{
    extern __shared__ char smc[];
    const uint32_t sb = smem_u32(smc);
    float* prm   = (float*)(smc + SM_PRM);
    float* ws    = (float*)(smc + SM_AHI);   // alias over A (+pad), dead before A written
    float* featf = (float*)(smc + SM_FEAT);

    const int t    = threadIdx.x;
    const int lane = t & 31;
    const int wid  = t >> 5;
    const int b    = blockIdx.y;
    const int n0   = blockIdx.x * TM;

    // ---- async staging helpers ----
    // feat: 8 channels x 128 pts x 9 k floats = 2304 x 16B, 9 per thread.
    auto stage_feat_async = [&](int ck) {
        if (ck >= NCH + 1) return;
#pragma unroll
        for (int j = 0; j < 9; j++) {
            const int idx = t + j * 256;
            const int cl  = idx / 288;
            const int rem = idx - cl * 288;
            const int c   = ck * CPC + cl;
            const char* src;
            uint32_t bytes = 16;
            if (c < 2)
                src = (const char*)(xy + ((size_t)(2 * b + c) * N_ + n0) * K_) + rem * 16;
            else if (c < CIN_)
                src = (const char*)(knnf + ((size_t)(CF_ * b + (c - 2)) * N_ + n0) * K_) + rem * 16;
            else { src = (const char*)xy; bytes = 0; }   // zero-fill
            cp16(sb + SM_FEAT + (uint32_t)idx * 16, src, bytes);
        }
    };
    // B: 704 x 16B per array (hi, lo)
    auto stage_B_async = [&](int ck) {
        if (ck >= NCH) return;
        const char* gh = (const char*)(g_Bhi + ck * (CO_ * 88));
        const char* gl = (const char*)(g_Blo + ck * (CO_ * 88));
        for (int i = t; i < 704; i += THREADS) {
            cp16(sb + SM_BHI + (uint32_t)i * 16, gh + i * 16, 16);
            cp16(sb + SM_BLO + (uint32_t)i * 16, gl + i * 16, 16);
        }
    };

    // prologue: prefetch feat(0), B(0)
    stage_feat_async(0);
    CP_COMMIT();                  // group F0
    stage_B_async(0);
    CP_COMMIT();                  // group B0

    // stage params
    if (t < 18)        prm[t] = w1[t];
    else if (t < 27)   prm[t] = b1[t - 18];
    else if (t < 108)  prm[t] = w2[t - 27];
    else if (t < 117)  prm[t] = b2[t - 108];
    else if (t < 181)  prm[t] = lb[t - 117];

    CP_WAIT(1);                   // F0 done (B0 may be pending)
    __syncthreads();

    // ---- WeightNet: ws[p][o*9+k] from staged xy (feat c0, c1) ----
    for (int task = t; task < TM * K_; task += THREADS) {
        const int p2 = task & 127;
        const int k  = task >> 7;
        const float x0 = featf[p2 * K_ + k];
        const float x1 = featf[TM * K_ + p2 * K_ + k];
        float h[O_];
#pragma unroll
        for (int j = 0; j < O_; j++)
            h[j] = leaky(fmaf(prm[2 * j], x0, fmaf(prm[2 * j + 1], x1, prm[18 + j])));
#pragma unroll
        for (int o = 0; o < O_; o++) {
            float v = prm[108 + o];
#pragma unroll
            for (int j = 0; j < O_; j++) v = fmaf(prm[27 + o * O_ + j], h[j], v);
            ws[p2 * 81 + o * 9 + k] = leaky(v);
        }
    }
    __syncthreads();

    // ---- per-thread w pairs (f32x2 over o) ----
    const int p  = t & 127;
    const int hh = t >> 7;
    uint64_t wpA[9], wpB[9];
    float w8[9];
    {
        const float* wr = ws + p * 81;
        const int ob = hh * 36;
#pragma unroll
        for (int k = 0; k < 9; k++) {
            wpA[k] = pack2(wr[ob + k],      wr[ob + 9 + k]);
            wpB[k] = pack2(wr[ob + 18 + k], wr[ob + 27 + k]);
            w8[k]  = wr[72 + k];
        }
    }
    __syncthreads();   // ws dead; A region writable

    // zero pad slots 72..79 of both A arrays (written once)
    {
        uint4 z = make_uint4(0, 0, 0, 0);
        char* padbase = (hh == 0) ? (smc + SM_AHI) : (smc + SM_ALO);
        ((uint4*)(padbase + 72 * ASTRIDE))[p] = z;
    }

    float acc[2][4][4];
#pragma unroll
    for (int mi = 0; mi < 2; mi++)
#pragma unroll
        for (int j = 0; j < 4; j++)
#pragma unroll
            for (int q = 0; q < 4; q++) acc[mi][j][q] = 0.0f;

    const uint32_t aAhi = sb + SM_AHI, aAlo = sb + SM_ALO;
    const uint32_t aBhi = sb + SM_BHI, aBlo = sb + SM_BLO;

    // warp tile: 32 points x 32 co
    const int mrow = (wid & 3) * 32;
    const int nc0j = (wid >> 2) * 4;   // first j (8 co each)

#pragma unroll 1
    for (int ck = 0; ck < NCH; ck++) {
        // ---- produce A chunk from staged features (feat(ck) ready) ----
#pragma unroll
        for (int ci = 0; ci < CPC; ci++) {
            const int kk0 = ci * 9 + (hh ? 4 : 0);
            const int nv  = hh ? 5 : 4;
            const float* fp = featf + ci * (TM * K_) + p * K_;
            float f[9];
#pragma unroll
            for (int k = 0; k < 9; k++) f[k] = fp[k];
            float v[5];
            uint64_t a0 = pack2(0.f, 0.f), a1 = pack2(0.f, 0.f);
            float s8 = 0.f;
#pragma unroll
            for (int k = 0; k < 9; k++) {
                const uint64_t ff = pack2(f[k], f[k]);
                a0 = fma2(ff, wpA[k], a0);
                a1 = fma2(ff, wpB[k], a1);
                if (hh) s8 = fmaf(f[k], w8[k], s8);
            }
            unpack2(a0, v[0], v[1]);
            unpack2(a1, v[2], v[3]);
            v[4] = s8;
#pragma unroll 5
            for (int j = 0; j < nv; j++) {
                const int kk = kk0 + j;
                const uint32_t off = (uint32_t)(kk * ASTRIDE) +
                    (((uint32_t)(p * 2)) ^ ((uint32_t)(kk & 7) << 4));
                __nv_bfloat16 hi = __float2bfloat16(v[j]);
                __nv_bfloat16 lo = __float2bfloat16(v[j] - __bfloat162float(hi));
                *(__nv_bfloat16*)(smc + SM_AHI + off) = hi;
                *(__nv_bfloat16*)(smc + SM_ALO + off) = lo;
            }
        }

        CP_WAIT(0);         // B(ck) landed
        __syncthreads();    // A(ck) + B(ck) visible to all

        // prefetch feat(ck+1) during mma (feat buffer is free now)
        stage_feat_async(ck + 1);
        CP_COMMIT();        // group F(ck+1)

        // ---- mma: warp tile 32p x 32co ----
        {
            const int r  = lane & 7;
            const int tq = lane >> 3;
#pragma unroll
            for (int s = 0; s < KSTEPS; s++) {
                const int krow = 16 * s + r + ((tq >> 1) << 3);
                const uint32_t sw = (uint32_t)(krow & 7) << 4;
                uint32_t ah[2][4], al[2][4];
#pragma unroll
                for (int mi = 0; mi < 2; mi++) {
                    const uint32_t mbyte =
                        (uint32_t)((mrow + mi * 16 + ((tq & 1) << 3)) * 2);
                    const uint32_t aoff = (uint32_t)(krow * ASTRIDE) + (mbyte ^ sw);
                    ldsm_x4_t(ah[mi], aAhi + aoff);
                    ldsm_x4_t(al[mi], aAlo + aoff);
                }
#pragma unroll
                for (int jp = 0; jp < 2; jp++) {
                    const int j = nc0j + 2 * jp;
                    const uint32_t boff =
                        (uint32_t)((8 * (j + (tq >> 1)) + r) * BSTRIDE +
                                   s * 32 + ((tq & 1) << 4));
                    uint32_t bh[4], bl[4];
                    ldsm_x4(bh, aBhi + boff);
                    ldsm_x4(bl, aBlo + boff);
#pragma unroll
                    for (int mi = 0; mi < 2; mi++) {
                        mma16816(acc[mi][2 * jp],     ah[mi], bh[0], bh[1]);
                        mma16816(acc[mi][2 * jp + 1], ah[mi], bh[2], bh[3]);
                        mma16816(acc[mi][2 * jp],     al[mi], bh[0], bh[1]);
                        mma16816(acc[mi][2 * jp + 1], al[mi], bh[2], bh[3]);
                        mma16816(acc[mi][2 * jp],     ah[mi], bl[0], bl[1]);
                        mma16816(acc[mi][2 * jp + 1], ah[mi], bl[2], bl[3]);
                    }
                }
            }
        }
        __syncthreads();    // A + B free

        // prefetch B(ck+1) during next production
        stage_B_async(ck + 1);
        CP_COMMIT();        // group B(ck+1)

        CP_WAIT(1);         // F(ck+1) done (B(ck+1) pending)
        __syncthreads();
    }

    // ---- epilogue: transpose through smem, coalesced float4 stores ----
    {
        float* tb = (float*)(smc + SM_AHI);   // [co][132] f32, conflict-free
        const int rr   = lane >> 2;
        const int col2 = (lane & 3) * 2;
#pragma unroll
        for (int mi = 0; mi < 2; mi++)
#pragma unroll
            for (int jp = 0; jp < 4; jp++) {
                const int co = (nc0j + jp) * 8 + col2;
                const int pr = mrow + mi * 16 + rr;
                tb[co * 132 + pr]           = acc[mi][jp][0];
                tb[(co + 1) * 132 + pr]     = acc[mi][jp][1];
                tb[co * 132 + pr + 8]       = acc[mi][jp][2];
                tb[(co + 1) * 132 + pr + 8] = acc[mi][jp][3];
            }
        __syncthreads();
#pragma unroll
        for (int j = 0; j < 8; j++) {
            const int i  = t + j * 256;
            const int co = i >> 5;
            const int u4 = i & 31;
            float4 v = *(float4*)(tb + co * 132 + u4 * 4);
            const float bi = prm[117 + co];
            v.x = leaky(v.x + bi);
            v.y = leaky(v.y + bi);
            v.z = leaky(v.z + bi);
            v.w = leaky(v.w + bi);
            *(float4*)(out + (size_t)(b * CO_ + co) * N_ + n0 + u4 * 4) = v;
        }
    }
}

extern "C" void kernel_launch(void* const* d_in, const int* in_sizes, int n_in,
                              void* d_out, int out_size)
{
    const float* xy   = (const float*)d_in[0];
    const float* knnf = (const float*)d_in[1];
    const float* w1   = (const float*)d_in[2];
    const float* b1   = (const float*)d_in[3];
    const float* w2   = (const float*)d_in[4];
    const float* b2   = (const float*)d_in[5];
    const float* lw   = (const float*)d_in[6];
    const float* lb   = (const float*)d_in[7];
    float* out = (float*)d_out;

    pc_prep<<<(NCH * CO_ * 88 + 255) / 256, 256>>>(lw);

    cudaFuncSetAttribute(pc_main, cudaFuncAttributeMaxDynamicSharedMemorySize, SM_TOT);
    dim3 grid(N_ / TM, B_);
    pc_main<<<grid, THREADS, SM_TOT>>>(xy, knnf, w1, b1, w2, b2, lb, out);
}

// round 11
// speedup vs baseline: 1.7164x; 1.7164x over previous
#include <cuda_runtime.h>
#include <cuda_fp16.h>
#include <cstdint>

// PointConv2d fused (round 6): mma.sync fp16 2-term compensated GEMM,
// cp.async pipelined, double-buffered B, 4x2 warp tiling.
// B=8, N=16384, K=9, C=64 -> CIN=66, O=9, CO=64, FAN=594.
// A = ah + al (fp16 pair, exact to 2^-24); B = fp16 single (err ~2^-12).

namespace {
constexpr int B_   = 8;
constexpr int N_   = 16384;
constexpr int K_   = 9;
constexpr int CF_  = 64;
constexpr int CIN_ = 66;
constexpr int O_   = 9;
constexpr int CO_  = 64;
constexpr int FAN_ = 594;

constexpr int TM      = 128;
constexpr int THREADS = 256;
constexpr int CPC     = 8;    // channels per chunk
constexpr int NCH     = 9;    // chunks
constexpr int SLOTS   = 80;   // padded k' slots per chunk
constexpr int KSTEPS  = 5;

constexpr int BSTRIDE = 176;  // B smem row stride bytes (160 data + pad)
constexpr int ASTRIDE = 256;  // A smem row stride bytes ([slot][p] fp16)

// shared memory byte offsets
constexpr int SM_PRM  = 0;                          // 181 floats -> 768
constexpr int SM_AHI  = 768;                        // 80*256 = 20480
constexpr int SM_ALO  = SM_AHI + SLOTS * ASTRIDE;   // 21248; A end 41728
constexpr int SM_B0   = 42240;                      // ws alias needs [768,42240)
constexpr int SM_B1   = SM_B0 + CO_ * BSTRIDE;      // 53504
constexpr int SM_FEAT = SM_B1 + CO_ * BSTRIDE;      // 64768
constexpr int SM_TOT  = SM_FEAT + CPC * TM * K_ * 4;  // 101632
// ws alias: [SM_AHI, SM_AHI+41472) = [768, 42240)  (dead before A written)
// epilogue transpose buffer alias: SM_AHI (64*132*4 = 33792)
}

// prepacked reordered fp16 linear weights: [chunk][co][88]
__device__ __half g_Bh[NCH * CO_ * 88];

// ---------------- helpers ----------------
__device__ __forceinline__ uint32_t smem_u32(const void* p) {
    uint32_t a;
    asm("{ .reg .u64 t; cvta.to.shared.u64 t, %1; cvt.u32.u64 %0, t; }"
        : "=r"(a) : "l"(p));
    return a;
}
__device__ __forceinline__ uint64_t pack2(float lo, float hi) {
    uint64_t r;
    asm("mov.b64 %0, {%1, %2};" : "=l"(r) : "f"(lo), "f"(hi));
    return r;
}
__device__ __forceinline__ void unpack2(uint64_t v, float& a, float& b) {
    asm("mov.b64 {%0, %1}, %2;" : "=f"(a), "=f"(b) : "l"(v));
}
__device__ __forceinline__ uint64_t fma2(uint64_t a, uint64_t b, uint64_t c) {
    uint64_t r;
    asm("fma.rn.f32x2 %0, %1, %2, %3;" : "=l"(r) : "l"(a), "l"(b), "l"(c));
    return r;
}
__device__ __forceinline__ void ldsm_x4(uint32_t* r, uint32_t a) {
    asm volatile("ldmatrix.sync.aligned.m8n8.x4.shared.b16 {%0,%1,%2,%3}, [%4];"
        : "=r"(r[0]), "=r"(r[1]), "=r"(r[2]), "=r"(r[3]) : "r"(a));
}
__device__ __forceinline__ void ldsm_x4_t(uint32_t* r, uint32_t a) {
    asm volatile("ldmatrix.sync.aligned.m8n8.x4.trans.shared.b16 {%0,%1,%2,%3}, [%4];"
        : "=r"(r[0]), "=r"(r[1]), "=r"(r[2]), "=r"(r[3]) : "r"(a));
}
__device__ __forceinline__ void mma16816(float* d, const uint32_t* a,
                                         uint32_t b0, uint32_t b1) {
    asm volatile("mma.sync.aligned.m16n8k16.row.col.f32.f16.f16.f32 "
        "{%0,%1,%2,%3}, {%4,%5,%6,%7}, {%8,%9}, {%0,%1,%2,%3};"
        : "+f"(d[0]), "+f"(d[1]), "+f"(d[2]), "+f"(d[3])
        : "r"(a[0]), "r"(a[1]), "r"(a[2]), "r"(a[3]), "r"(b0), "r"(b1));
}
__device__ __forceinline__ void cp16(uint32_t dst, const void* src, uint32_t bytes) {
    asm volatile("cp.async.cg.shared.global [%0], [%1], 16, %2;"
        :: "r"(dst), "l"(src), "r"(bytes) : "memory");
}
#define CP_COMMIT() asm volatile("cp.async.commit_group;" ::: "memory")
#define CP_WAIT(n)  asm volatile("cp.async.wait_group %0;" :: "n"(n) : "memory")
__device__ __forceinline__ float leaky(float x) { return fmaxf(x, 0.1f * x); }

// ---------------- prep: reorder lin_w, fp16 ----------------
__global__ void pc_prep(const float* __restrict__ lw) {
    int idx = blockIdx.x * blockDim.x + threadIdx.x;
    if (idx >= NCH * CO_ * 88) return;
    const int kk = idx % 88;
    const int co = (idx / 88) % CO_;
    const int ck = idx / (88 * CO_);
    float v = 0.0f;
    if (kk < 72) {
        const int c = ck * CPC + kk / 9;
        const int o = kk % 9;
        if (c < CIN_) v = lw[co * FAN_ + o * CIN_ + c];
    }
    g_Bh[idx] = __float2half_rn(v);
}

// ---------------- main kernel ----------------
__global__ __launch_bounds__(THREADS, 2)
void pc_main(const float* __restrict__ xy,    // [B,2,N,K]
             const float* __restrict__ knnf,  // [B,64,N,K]
             const float* __restrict__ w1, const float* __restrict__ b1,
             const float* __restrict__ w2, const float* __restrict__ b2,
             const float* __restrict__ lb,    // [64]
             float* __restrict__ out)         // [B,64,N]
{
    extern __shared__ char smc[];
    const uint32_t sb = smem_u32(smc);
    float* prm   = (float*)(smc + SM_PRM);
    float* ws    = (float*)(smc + SM_AHI);   // alias over A (+pad), dead before A written
    float* featf = (float*)(smc + SM_FEAT);

    const int t    = threadIdx.x;
    const int lane = t & 31;
    const int wid  = t >> 5;
    const int b    = blockIdx.y;
    const int n0   = blockIdx.x * TM;

    // ---- async staging helpers ----
    auto stage_feat_async = [&](int ck) {
        if (ck >= NCH) return;
#pragma unroll
        for (int j = 0; j < 9; j++) {
            const int idx = t + j * 256;
            const int cl  = idx / 288;
            const int rem = idx - cl * 288;
            const int c   = ck * CPC + cl;
            const char* src;
            uint32_t bytes = 16;
            if (c < 2)
                src = (const char*)(xy + ((size_t)(2 * b + c) * N_ + n0) * K_) + rem * 16;
            else if (c < CIN_)
                src = (const char*)(knnf + ((size_t)(CF_ * b + (c - 2)) * N_ + n0) * K_) + rem * 16;
            else { src = (const char*)xy; bytes = 0; }   // zero-fill
            cp16(sb + SM_FEAT + (uint32_t)idx * 16, src, bytes);
        }
    };
    auto stage_B_async = [&](int ck) {
        if (ck >= NCH) return;
        const uint32_t dst = sb + ((ck & 1) ? SM_B1 : SM_B0);
        const char* gh = (const char*)(g_Bh + ck * (CO_ * 88));
        for (int i = t; i < 704; i += THREADS)
            cp16(dst + (uint32_t)i * 16, gh + i * 16, 16);
    };

    // prologue: prefetch feat(0), B(0)
    stage_feat_async(0);
    CP_COMMIT();                  // group F0
    stage_B_async(0);
    CP_COMMIT();                  // group B0

    // stage params
    if (t < 18)        prm[t] = w1[t];
    else if (t < 27)   prm[t] = b1[t - 18];
    else if (t < 108)  prm[t] = w2[t - 27];
    else if (t < 117)  prm[t] = b2[t - 108];
    else if (t < 181)  prm[t] = lb[t - 117];

    CP_WAIT(1);                   // F0 done (B0 pending)
    __syncthreads();

    // ---- WeightNet: ws[p][o*9+k] from staged xy (feat c0, c1) ----
    for (int task = t; task < TM * K_; task += THREADS) {
        const int p2 = task & 127;
        const int k  = task >> 7;
        const float x0 = featf[p2 * K_ + k];
        const float x1 = featf[TM * K_ + p2 * K_ + k];
        float h[O_];
#pragma unroll
        for (int j = 0; j < O_; j++)
            h[j] = leaky(fmaf(prm[2 * j], x0, fmaf(prm[2 * j + 1], x1, prm[18 + j])));
#pragma unroll
        for (int o = 0; o < O_; o++) {
            float v = prm[108 + o];
#pragma unroll
            for (int j = 0; j < O_; j++) v = fmaf(prm[27 + o * O_ + j], h[j], v);
            ws[p2 * 81 + o * 9 + k] = leaky(v);
        }
    }
    __syncthreads();

    // ---- per-thread w pairs (f32x2 over o) ----
    const int p  = t & 127;
    const int hh = t >> 7;
    uint64_t wpA[9], wpB[9];
    float w8[9];
    {
        const float* wr = ws + p * 81;
        const int ob = hh * 36;
#pragma unroll
        for (int k = 0; k < 9; k++) {
            wpA[k] = pack2(wr[ob + k],      wr[ob + 9 + k]);
            wpB[k] = pack2(wr[ob + 18 + k], wr[ob + 27 + k]);
            w8[k]  = wr[72 + k];
        }
    }
    __syncthreads();   // ws dead; A region writable

    // zero pad slots 72..79 of both A arrays (written once)
    {
        uint4 z = make_uint4(0, 0, 0, 0);
        char* padbase = (hh == 0) ? (smc + SM_AHI) : (smc + SM_ALO);
        ((uint4*)(padbase + 72 * ASTRIDE))[p] = z;
    }

    float acc[2][4][4];
#pragma unroll
    for (int mi = 0; mi < 2; mi++)
#pragma unroll
        for (int j = 0; j < 4; j++)
#pragma unroll
            for (int q = 0; q < 4; q++) acc[mi][j][q] = 0.0f;

    const uint32_t aAhi = sb + SM_AHI, aAlo = sb + SM_ALO;

    // warp tile: 32 points x 32 co
    const int mrow = (wid & 3) * 32;
    const int nc0j = (wid >> 2) * 4;

#pragma unroll 1
    for (int ck = 0; ck < NCH; ck++) {
        // ---- produce A chunk from staged features (feat(ck) ready) ----
#pragma unroll
        for (int ci = 0; ci < CPC; ci++) {
            const int kk0 = ci * 9 + (hh ? 4 : 0);
            const int nv  = hh ? 5 : 4;
            const float* fp = featf + ci * (TM * K_) + p * K_;
            float f[9];
#pragma unroll
            for (int k = 0; k < 9; k++) f[k] = fp[k];
            float v[5];
            uint64_t a0 = pack2(0.f, 0.f), a1 = pack2(0.f, 0.f);
            float s8 = 0.f;
#pragma unroll
            for (int k = 0; k < 9; k++) {
                const uint64_t ff = pack2(f[k], f[k]);
                a0 = fma2(ff, wpA[k], a0);
                a1 = fma2(ff, wpB[k], a1);
                if (hh) s8 = fmaf(f[k], w8[k], s8);
            }
            unpack2(a0, v[0], v[1]);
            unpack2(a1, v[2], v[3]);
            v[4] = s8;
#pragma unroll 5
            for (int j = 0; j < nv; j++) {
                const int kk = kk0 + j;
                const uint32_t off = (uint32_t)(kk * ASTRIDE) +
                    (((uint32_t)(p * 2)) ^ ((uint32_t)(kk & 7) << 4));
                __half hi = __float2half_rn(v[j]);
                __half lo = __float2half_rn(v[j] - __half2float(hi));
                *(__half*)(smc + SM_AHI + off) = hi;
                *(__half*)(smc + SM_ALO + off) = lo;
            }
        }

        CP_WAIT(0);         // B(ck) landed (had >= 1 full phase of slack)
        __syncthreads();    // A(ck) + B(ck) visible to all

        // prefetch feat(ck+1) and B(ck+1) during mma (other buffers)
        stage_feat_async(ck + 1);
        CP_COMMIT();        // group F(ck+1)
        stage_B_async(ck + 1);
        CP_COMMIT();        // group B(ck+1)

        // ---- mma: warp tile 32p x 32co, 2-term fp16 ----
        {
            const uint32_t aBh = sb + ((ck & 1) ? SM_B1 : SM_B0);
            const int r  = lane & 7;
            const int tq = lane >> 3;
#pragma unroll
            for (int s = 0; s < KSTEPS; s++) {
                const int krow = 16 * s + r + ((tq >> 1) << 3);
                const uint32_t sw = (uint32_t)(krow & 7) << 4;
                uint32_t ah[2][4], al[2][4];
#pragma unroll
                for (int mi = 0; mi < 2; mi++) {
                    const uint32_t mbyte =
                        (uint32_t)((mrow + mi * 16 + ((tq & 1) << 3)) * 2);
                    const uint32_t aoff = (uint32_t)(krow * ASTRIDE) + (mbyte ^ sw);
                    ldsm_x4_t(ah[mi], aAhi + aoff);
                    ldsm_x4_t(al[mi], aAlo + aoff);
                }
#pragma unroll
                for (int jp = 0; jp < 2; jp++) {
                    const int j = nc0j + 2 * jp;
                    const uint32_t boff =
                        (uint32_t)((8 * (j + (tq >> 1)) + r) * BSTRIDE +
                                   s * 32 + ((tq & 1) << 4));
                    uint32_t bh[4];
                    ldsm_x4(bh, aBh + boff);
#pragma unroll
                    for (int mi = 0; mi < 2; mi++) {
                        mma16816(acc[mi][2 * jp],     ah[mi], bh[0], bh[1]);
                        mma16816(acc[mi][2 * jp + 1], ah[mi], bh[2], bh[3]);
                        mma16816(acc[mi][2 * jp],     al[mi], bh[0], bh[1]);
                        mma16816(acc[mi][2 * jp + 1], al[mi], bh[2], bh[3]);
                    }
                }
            }
        }
        CP_WAIT(1);         // F(ck+1) done (B(ck+1) may be pending)
        __syncthreads();    // A free; feat(ck+1) visible
    }

    // ---- epilogue: transpose through smem, coalesced float4 stores ----
    {
        float* tb = (float*)(smc + SM_AHI);   // [co][132] f32, conflict-free
        const int rr   = lane >> 2;
        const int col2 = (lane & 3) * 2;
#pragma unroll
        for (int mi = 0; mi < 2; mi++)
#pragma unroll
            for (int jp = 0; jp < 4; jp++) {
                const int co = (nc0j + jp) * 8 + col2;
                const int pr = mrow + mi * 16 + rr;
                tb[co * 132 + pr]           = acc[mi][jp][0];
                tb[(co + 1) * 132 + pr]     = acc[mi][jp][1];
                tb[co * 132 + pr + 8]       = acc[mi][jp][2];
                tb[(co + 1) * 132 + pr + 8] = acc[mi][jp][3];
            }
        __syncthreads();
#pragma unroll
        for (int j = 0; j < 8; j++) {
            const int i  = t + j * 256;
            const int co = i >> 5;
            const int u4 = i & 31;
            float4 v = *(float4*)(tb + co * 132 + u4 * 4);
            const float bi = prm[117 + co];
            v.x = leaky(v.x + bi);
            v.y = leaky(v.y + bi);
            v.z = leaky(v.z + bi);
            v.w = leaky(v.w + bi);
            *(float4*)(out + (size_t)(b * CO_ + co) * N_ + n0 + u4 * 4) = v;
        }
    }
}

extern "C" void kernel_launch(void* const* d_in, const int* in_sizes, int n_in,
                              void* d_out, int out_size)
{
    const float* xy   = (const float*)d_in[0];
    const float* knnf = (const float*)d_in[1];
    const float* w1   = (const float*)d_in[2];
    const float* b1   = (const float*)d_in[3];
    const float* w2   = (const float*)d_in[4];
    const float* b2   = (const float*)d_in[5];
    const float* lw   = (const float*)d_in[6];
    const float* lb   = (const float*)d_in[7];
    float* out = (float*)d_out;

    pc_prep<<<(NCH * CO_ * 88 + 255) / 256, 256>>>(lw);

    cudaFuncSetAttribute(pc_main, cudaFuncAttributeMaxDynamicSharedMemorySize, SM_TOT);
    dim3 grid(N_ / TM, B_);
    pc_main<<<grid, THREADS, SM_TOT>>>(xy, knnf, w1, b1, w2, b2, lb, out);
}

// round 12
// speedup vs baseline: 1.9320x; 1.1256x over previous
#include <cuda_runtime.h>
#include <cuda_fp16.h>
#include <cstdint>

// PointConv2d fused (round 7): plain fp16 mma.sync GEMM (fp32 accum),
// cp.async pipelined, double-buffered B, 4x2 warp tiling.
// B=8, N=16384, K=9, C=64 -> CIN=66, O=9, CO=64, FAN=594.
// A = fp16, B = fp16; expected rel_err ~4e-4 (gate 1e-3).

namespace {
constexpr int B_   = 8;
constexpr int N_   = 16384;
constexpr int K_   = 9;
constexpr int CF_  = 64;
constexpr int CIN_ = 66;
constexpr int O_   = 9;
constexpr int CO_  = 64;
constexpr int FAN_ = 594;

constexpr int TM      = 128;
constexpr int THREADS = 256;
constexpr int CPC     = 8;    // channels per chunk
constexpr int NCH     = 9;    // chunks
constexpr int SLOTS   = 80;   // padded k' slots per chunk
constexpr int KSTEPS  = 5;

constexpr int BSTRIDE = 176;  // B smem row stride bytes
constexpr int ASTRIDE = 256;  // A smem row stride bytes ([slot][p] fp16)

// shared memory byte offsets (identical map to round 6; ALO region now unused)
constexpr int SM_PRM  = 0;                          // 181 floats -> 768
constexpr int SM_AHI  = 768;                        // 80*256 = 20480
constexpr int SM_B0   = 42240;                      // ws alias = [768, 42240)
constexpr int SM_B1   = SM_B0 + CO_ * BSTRIDE;      // 53504
constexpr int SM_FEAT = SM_B1 + CO_ * BSTRIDE;      // 64768
constexpr int SM_TOT  = SM_FEAT + CPC * TM * K_ * 4;  // 101632
// ws alias: [768, 42240) (dead before A written)
// epilogue transpose buffer alias: SM_AHI (64*132*4 = 33792)
}

// prepacked reordered fp16 linear weights: [chunk][co][88]
__device__ __half g_Bh[NCH * CO_ * 88];

// ---------------- helpers ----------------
__device__ __forceinline__ uint32_t smem_u32(const void* p) {
    uint32_t a;
    asm("{ .reg .u64 t; cvta.to.shared.u64 t, %1; cvt.u32.u64 %0, t; }"
        : "=r"(a) : "l"(p));
    return a;
}
__device__ __forceinline__ uint64_t pack2(float lo, float hi) {
    uint64_t r;
    asm("mov.b64 %0, {%1, %2};" : "=l"(r) : "f"(lo), "f"(hi));
    return r;
}
__device__ __forceinline__ void unpack2(uint64_t v, float& a, float& b) {
    asm("mov.b64 {%0, %1}, %2;" : "=f"(a), "=f"(b) : "l"(v));
}
__device__ __forceinline__ uint64_t fma2(uint64_t a, uint64_t b, uint64_t c) {
    uint64_t r;
    asm("fma.rn.f32x2 %0, %1, %2, %3;" : "=l"(r) : "l"(a), "l"(b), "l"(c));
    return r;
}
__device__ __forceinline__ void ldsm_x4(uint32_t* r, uint32_t a) {
    asm volatile("ldmatrix.sync.aligned.m8n8.x4.shared.b16 {%0,%1,%2,%3}, [%4];"
        : "=r"(r[0]), "=r"(r[1]), "=r"(r[2]), "=r"(r[3]) : "r"(a));
}
__device__ __forceinline__ void ldsm_x4_t(uint32_t* r, uint32_t a) {
    asm volatile("ldmatrix.sync.aligned.m8n8.x4.trans.shared.b16 {%0,%1,%2,%3}, [%4];"
        : "=r"(r[0]), "=r"(r[1]), "=r"(r[2]), "=r"(r[3]) : "r"(a));
}
__device__ __forceinline__ void mma16816(float* d, const uint32_t* a,
                                         uint32_t b0, uint32_t b1) {
    asm volatile("mma.sync.aligned.m16n8k16.row.col.f32.f16.f16.f32 "
        "{%0,%1,%2,%3}, {%4,%5,%6,%7}, {%8,%9}, {%0,%1,%2,%3};"
        : "+f"(d[0]), "+f"(d[1]), "+f"(d[2]), "+f"(d[3])
        : "r"(a[0]), "r"(a[1]), "r"(a[2]), "r"(a[3]), "r"(b0), "r"(b1));
}
__device__ __forceinline__ void cp16(uint32_t dst, const void* src, uint32_t bytes) {
    asm volatile("cp.async.cg.shared.global [%0], [%1], 16, %2;"
        :: "r"(dst), "l"(src), "r"(bytes) : "memory");
}
#define CP_COMMIT() asm volatile("cp.async.commit_group;" ::: "memory")
#define CP_WAIT(n)  asm volatile("cp.async.wait_group %0;" :: "n"(n) : "memory")
__device__ __forceinline__ float leaky(float x) { return fmaxf(x, 0.1f * x); }

// ---------------- prep: reorder lin_w, fp16 ----------------
__global__ void pc_prep(const float* __restrict__ lw) {
    int idx = blockIdx.x * blockDim.x + threadIdx.x;
    if (idx >= NCH * CO_ * 88) return;
    const int kk = idx % 88;
    const int co = (idx / 88) % CO_;
    const int ck = idx / (88 * CO_);
    float v = 0.0f;
    if (kk < 72) {
        const int c = ck * CPC + kk / 9;
        const int o = kk % 9;
        if (c < CIN_) v = lw[co * FAN_ + o * CIN_ + c];
    }
    g_Bh[idx] = __float2half_rn(v);
}

// ---------------- main kernel ----------------
__global__ __launch_bounds__(THREADS, 2)
void pc_main(const float* __restrict__ xy,    // [B,2,N,K]
             const float* __restrict__ knnf,  // [B,64,N,K]
             const float* __restrict__ w1, const float* __restrict__ b1,
             const float* __restrict__ w2, const float* __restrict__ b2,
             const float* __restrict__ lb,    // [64]
             float* __restrict__ out)         // [B,64,N]
{
    extern __shared__ char smc[];
    const uint32_t sb = smem_u32(smc);
    float* prm   = (float*)(smc + SM_PRM);
    float* ws    = (float*)(smc + SM_AHI);   // alias [768,42240), dead before A written
    float* featf = (float*)(smc + SM_FEAT);

    const int t    = threadIdx.x;
    const int lane = t & 31;
    const int wid  = t >> 5;
    const int b    = blockIdx.y;
    const int n0   = blockIdx.x * TM;

    // ---- async staging helpers ----
    auto stage_feat_async = [&](int ck) {
        if (ck >= NCH) return;
#pragma unroll
        for (int j = 0; j < 9; j++) {
            const int idx = t + j * 256;
            const int cl  = idx / 288;
            const int rem = idx - cl * 288;
            const int c   = ck * CPC + cl;
            const char* src;
            uint32_t bytes = 16;
            if (c < 2)
                src = (const char*)(xy + ((size_t)(2 * b + c) * N_ + n0) * K_) + rem * 16;
            else if (c < CIN_)
                src = (const char*)(knnf + ((size_t)(CF_ * b + (c - 2)) * N_ + n0) * K_) + rem * 16;
            else { src = (const char*)xy; bytes = 0; }   // zero-fill
            cp16(sb + SM_FEAT + (uint32_t)idx * 16, src, bytes);
        }
    };
    auto stage_B_async = [&](int ck) {
        if (ck >= NCH) return;
        const uint32_t dst = sb + ((ck & 1) ? SM_B1 : SM_B0);
        const char* gh = (const char*)(g_Bh + ck * (CO_ * 88));
        for (int i = t; i < 704; i += THREADS)
            cp16(dst + (uint32_t)i * 16, gh + i * 16, 16);
    };

    // prologue: prefetch feat(0), B(0)
    stage_feat_async(0);
    CP_COMMIT();                  // group F0
    stage_B_async(0);
    CP_COMMIT();                  // group B0

    // stage params
    if (t < 18)        prm[t] = w1[t];
    else if (t < 27)   prm[t] = b1[t - 18];
    else if (t < 108)  prm[t] = w2[t - 27];
    else if (t < 117)  prm[t] = b2[t - 108];
    else if (t < 181)  prm[t] = lb[t - 117];

    CP_WAIT(1);                   // F0 done (B0 pending)
    __syncthreads();

    // ---- WeightNet: ws[p][o*9+k] from staged xy (feat c0, c1) ----
    for (int task = t; task < TM * K_; task += THREADS) {
        const int p2 = task & 127;
        const int k  = task >> 7;
        const float x0 = featf[p2 * K_ + k];
        const float x1 = featf[TM * K_ + p2 * K_ + k];
        float h[O_];
#pragma unroll
        for (int j = 0; j < O_; j++)
            h[j] = leaky(fmaf(prm[2 * j], x0, fmaf(prm[2 * j + 1], x1, prm[18 + j])));
#pragma unroll
        for (int o = 0; o < O_; o++) {
            float v = prm[108 + o];
#pragma unroll
            for (int j = 0; j < O_; j++) v = fmaf(prm[27 + o * O_ + j], h[j], v);
            ws[p2 * 81 + o * 9 + k] = leaky(v);
        }
    }
    __syncthreads();

    // ---- per-thread w pairs (f32x2 over o) ----
    const int p  = t & 127;
    const int hh = t >> 7;
    uint64_t wpA[9], wpB[9];
    float w8[9];
    {
        const float* wr = ws + p * 81;
        const int ob = hh * 36;
#pragma unroll
        for (int k = 0; k < 9; k++) {
            wpA[k] = pack2(wr[ob + k],      wr[ob + 9 + k]);
            wpB[k] = pack2(wr[ob + 18 + k], wr[ob + 27 + k]);
            w8[k]  = wr[72 + k];
        }
    }
    __syncthreads();   // ws dead; A region writable

    // zero pad slots 72..79 of A (8 rows x 256B = 2048B = 128 uint4)
    if (t < 128) {
        uint4 z = make_uint4(0, 0, 0, 0);
        ((uint4*)(smc + SM_AHI + 72 * ASTRIDE))[t] = z;
    }

    float acc[2][4][4];
#pragma unroll
    for (int mi = 0; mi < 2; mi++)
#pragma unroll
        for (int j = 0; j < 4; j++)
#pragma unroll
            for (int q = 0; q < 4; q++) acc[mi][j][q] = 0.0f;

    const uint32_t aAhi = sb + SM_AHI;

    // warp tile: 32 points x 32 co
    const int mrow = (wid & 3) * 32;
    const int nc0j = (wid >> 2) * 4;

#pragma unroll 1
    for (int ck = 0; ck < NCH; ck++) {
        // ---- produce A chunk from staged features (feat(ck) ready) ----
#pragma unroll
        for (int ci = 0; ci < CPC; ci++) {
            const int kk0 = ci * 9 + (hh ? 4 : 0);
            const int nv  = hh ? 5 : 4;
            const float* fp = featf + ci * (TM * K_) + p * K_;
            float f[9];
#pragma unroll
            for (int k = 0; k < 9; k++) f[k] = fp[k];
            float v[5];
            uint64_t a0 = pack2(0.f, 0.f), a1 = pack2(0.f, 0.f);
            float s8 = 0.f;
#pragma unroll
            for (int k = 0; k < 9; k++) {
                const uint64_t ff = pack2(f[k], f[k]);
                a0 = fma2(ff, wpA[k], a0);
                a1 = fma2(ff, wpB[k], a1);
                if (hh) s8 = fmaf(f[k], w8[k], s8);
            }
            unpack2(a0, v[0], v[1]);
            unpack2(a1, v[2], v[3]);
            v[4] = s8;
#pragma unroll 5
            for (int j = 0; j < nv; j++) {
                const int kk = kk0 + j;
                const uint32_t off = (uint32_t)(kk * ASTRIDE) +
                    (((uint32_t)(p * 2)) ^ ((uint32_t)(kk & 7) << 4));
                *(__half*)(smc + SM_AHI + off) = __float2half_rn(v[j]);
            }
        }

        CP_WAIT(0);         // B(ck) landed
        __syncthreads();    // A(ck) + B(ck) visible to all

        // prefetch feat(ck+1) and B(ck+1) during mma
        stage_feat_async(ck + 1);
        CP_COMMIT();        // group F(ck+1)
        stage_B_async(ck + 1);
        CP_COMMIT();        // group B(ck+1)

        // ---- mma: warp tile 32p x 32co, plain fp16 ----
        {
            const uint32_t aBh = sb + ((ck & 1) ? SM_B1 : SM_B0);
            const int r  = lane & 7;
            const int tq = lane >> 3;
#pragma unroll
            for (int s = 0; s < KSTEPS; s++) {
                const int krow = 16 * s + r + ((tq >> 1) << 3);
                const uint32_t sw = (uint32_t)(krow & 7) << 4;
                uint32_t ah[2][4];
#pragma unroll
                for (int mi = 0; mi < 2; mi++) {
                    const uint32_t mbyte =
                        (uint32_t)((mrow + mi * 16 + ((tq & 1) << 3)) * 2);
                    const uint32_t aoff = (uint32_t)(krow * ASTRIDE) + (mbyte ^ sw);
                    ldsm_x4_t(ah[mi], aAhi + aoff);
                }
#pragma unroll
                for (int jp = 0; jp < 2; jp++) {
                    const int j = nc0j + 2 * jp;
                    const uint32_t boff =
                        (uint32_t)((8 * (j + (tq >> 1)) + r) * BSTRIDE +
                                   s * 32 + ((tq & 1) << 4));
                    uint32_t bh[4];
                    ldsm_x4(bh, aBh + boff);
#pragma unroll
                    for (int mi = 0; mi < 2; mi++) {
                        mma16816(acc[mi][2 * jp],     ah[mi], bh[0], bh[1]);
                        mma16816(acc[mi][2 * jp + 1], ah[mi], bh[2], bh[3]);
                    }
                }
            }
        }
        CP_WAIT(1);         // F(ck+1) done (B(ck+1) may be pending)
        __syncthreads();    // A free; feat(ck+1) visible
    }

    // ---- epilogue: transpose through smem, coalesced float4 stores ----
    {
        float* tb = (float*)(smc + SM_AHI);   // [co][132] f32, conflict-free
        const int rr   = lane >> 2;
        const int col2 = (lane & 3) * 2;
#pragma unroll
        for (int mi = 0; mi < 2; mi++)
#pragma unroll
            for (int jp = 0; jp < 4; jp++) {
                const int co = (nc0j + jp) * 8 + col2;
                const int pr = mrow + mi * 16 + rr;
                tb[co * 132 + pr]           = acc[mi][jp][0];
                tb[(co + 1) * 132 + pr]     = acc[mi][jp][1];
                tb[co * 132 + pr + 8]       = acc[mi][jp][2];
                tb[(co + 1) * 132 + pr + 8] = acc[mi][jp][3];
            }
        __syncthreads();
#pragma unroll
        for (int j = 0; j < 8; j++) {
            const int i  = t + j * 256;
            const int co = i >> 5;
            const int u4 = i & 31;
            float4 v = *(float4*)(tb + co * 132 + u4 * 4);
            const float bi = prm[117 + co];
            v.x = leaky(v.x + bi);
            v.y = leaky(v.y + bi);
            v.z = leaky(v.z + bi);
            v.w = leaky(v.w + bi);
            *(float4*)(out + (size_t)(b * CO_ + co) * N_ + n0 + u4 * 4) = v;
        }
    }
}

extern "C" void kernel_launch(void* const* d_in, const int* in_sizes, int n_in,
                              void* d_out, int out_size)
{
    const float* xy   = (const float*)d_in[0];
    const float* knnf = (const float*)d_in[1];
    const float* w1   = (const float*)d_in[2];
    const float* b1   = (const float*)d_in[3];
    const float* w2   = (const float*)d_in[4];
    const float* b2   = (const float*)d_in[5];
    const float* lw   = (const float*)d_in[6];
    const float* lb   = (const float*)d_in[7];
    float* out = (float*)d_out;

    pc_prep<<<(NCH * CO_ * 88 + 255) / 256, 256>>>(lw);

    cudaFuncSetAttribute(pc_main, cudaFuncAttributeMaxDynamicSharedMemorySize, SM_TOT);
    dim3 grid(N_ / TM, B_);
    pc_main<<<grid, THREADS, SM_TOT>>>(xy, knnf, w1, b1, w2, b2, lb, out);
}